// round 8
// baseline (speedup 1.0000x reference)
#include <cuda_runtime.h>
#include <math.h>

#define T_STEPS 512
#define BATCH   64
#define INDIM   1024
#define HDIM    1024
#define BH      (BATCH * HDIM)      // 65536
#define NCTA    128
#define NTHR    256

// ---------------- device scratch (static, allowed) ----------------
__device__ float g_X0T[(size_t)T_STEPS * BH]; // input proj + layer-0 biases, layout [t][j][b]
__device__ float g_h0T[BH];                   // layer-0 hidden, layout [k][b]
__device__ float g_h1T[BH];                   // layer-1 hidden, layout [k][b]
__device__ float g_ppA[4][BH];                // phase-A split-K partials, [sub][j*64+b]
__device__ float g_ppB[4][BH];                // phase-B partials (mat,khalf), [sub][j*64+b]
__device__ unsigned g_cnt;                    // barrier arrival counter
__device__ unsigned g_gen;                    // barrier generation

// =================================================================
// Precompute: X0T[t][n][b] = sum_k input[t,b,k]*W_ih0[n,k] + b_ih0[n] + b_hh0[n]
// m = t*64+b over T*B rows; 64x64x16 smem-tiled SGEMM; store TRANSPOSED.
// =================================================================
__global__ __launch_bounds__(256) void precompute_kernel(
    const float* __restrict__ X,    // [T*B, IN]
    const float* __restrict__ W,    // [H, IN]
    const float* __restrict__ b1,
    const float* __restrict__ b2)
{
    const int BM = 64, BN = 64, BK = 16;
    __shared__ float As[BK][BM];
    __shared__ float Ws[BK][BN];

    int m0  = blockIdx.y * BM;      // = t*64 (BM==BATCH)
    int n0  = blockIdx.x * BN;
    int tid = threadIdx.x;
    int t   = blockIdx.y;

    int tm4 = (tid / 16) * 4;
    int tn4 = (tid % 16) * 4;
    int lr  = tid / 4;
    int lk  = (tid % 4) * 4;

    float acc[4][4];
    #pragma unroll
    for (int i = 0; i < 4; i++)
        #pragma unroll
        for (int j = 0; j < 4; j++) acc[i][j] = 0.0f;

    for (int k0 = 0; k0 < INDIM; k0 += BK) {
        float4 av = *(const float4*)&X[(size_t)(m0 + lr) * INDIM + k0 + lk];
        float4 wv = *(const float4*)&W[(size_t)(n0 + lr) * INDIM + k0 + lk];
        __syncthreads();
        As[lk + 0][lr] = av.x; As[lk + 1][lr] = av.y;
        As[lk + 2][lr] = av.z; As[lk + 3][lr] = av.w;
        Ws[lk + 0][lr] = wv.x; Ws[lk + 1][lr] = wv.y;
        Ws[lk + 2][lr] = wv.z; Ws[lk + 3][lr] = wv.w;
        __syncthreads();
        #pragma unroll
        for (int kk = 0; kk < BK; kk++) {
            float4 a = *(const float4*)&As[kk][tm4];
            float4 w = *(const float4*)&Ws[kk][tn4];
            float av4[4] = {a.x, a.y, a.z, a.w};
            float wv4[4] = {w.x, w.y, w.z, w.w};
            #pragma unroll
            for (int i = 0; i < 4; i++)
                #pragma unroll
                for (int j = 0; j < 4; j++)
                    acc[i][j] += av4[i] * wv4[j];
        }
    }

    float bias[4];
    #pragma unroll
    for (int j = 0; j < 4; j++)
        bias[j] = b1[n0 + tn4 + j] + b2[n0 + tn4 + j];

    // store transposed: X0T[t][n][b], b = tm4+i
    #pragma unroll
    for (int i = 0; i < 4; i++)
        #pragma unroll
        for (int j = 0; j < 4; j++)
            g_X0T[(size_t)t * BH + (size_t)(n0 + tn4 + j) * 64 + (tm4 + i)]
                = acc[i][j] + bias[j];
}

// =================================================================
// Persistent recurrent kernel: 128 co-resident CTAs, software grid barrier.
// =================================================================
__device__ __forceinline__ void grid_barrier(unsigned& gen)
{
    __syncthreads();
    if (threadIdx.x == 0) {
        __threadfence();
        unsigned a = atomicAdd(&g_cnt, 1u);
        if (a == NCTA - 1) {
            g_cnt = 0;                 // all arrived; safe before release
            __threadfence();
            atomicAdd(&g_gen, 1u);     // release
        } else {
            while (*(volatile unsigned*)&g_gen == gen) { }
            __threadfence();
        }
    }
    __syncthreads();
    gen++;
}

// One GEMM phase over this CTA's resident weight slice.
// Wsm: [KTOT][32] (k-major, j fast).  hsrc: [KTOT][64] global slice (k-major).
// pp: partial output base (j0*64 already applied): [32j][64b].
// Thread tile: 2j x 4b.  Hs: double-buffered [2][32][64] chunk staging.
__device__ __forceinline__ void gemm_phase(
    const float* __restrict__ Wsm,
    const float* __restrict__ hsrc,
    float* __restrict__ pp,
    float* Hs, int KTOT, int tid)
{
    const int jg = tid & 15;     // j pair index
    const int bg = tid >> 4;     // b quad index
    float a00 = 0.f, a01 = 0.f, a02 = 0.f, a03 = 0.f;
    float a10 = 0.f, a11 = 0.f, a12 = 0.f, a13 = 0.f;

    const float4* h4 = (const float4*)hsrc;   // chunk = 512 float4s
    float4 p0 = h4[tid];
    float4 p1 = h4[tid + 256];
    const int nch = KTOT >> 5;

    for (int ch = 0; ch < nch; ch++) {
        float* H = Hs + (ch & 1) * 2048;
        ((float4*)H)[tid]       = p0;
        ((float4*)H)[tid + 256] = p1;
        __syncthreads();
        if (ch + 1 < nch) {
            p0 = h4[(ch + 1) * 512 + tid];
            p1 = h4[(ch + 1) * 512 + tid + 256];
        }
        const float* Wc = Wsm + (ch << 5) * 32;
        #pragma unroll
        for (int k = 0; k < 32; k++) {
            float2 w = *(const float2*)&Wc[k * 32 + 2 * jg];
            float4 h = *(const float4*)&H[k * 64 + 4 * bg];
            a00 += w.x * h.x; a01 += w.x * h.y; a02 += w.x * h.z; a03 += w.x * h.w;
            a10 += w.y * h.x; a11 += w.y * h.y; a12 += w.y * h.z; a13 += w.y * h.w;
        }
        __syncthreads();
    }
    float4 v0 = make_float4(a00, a01, a02, a03);
    float4 v1 = make_float4(a10, a11, a12, a13);
    *(float4*)&pp[(2 * jg + 0) * 64 + 4 * bg] = v0;
    *(float4*)&pp[(2 * jg + 1) * 64 + 4 * bg] = v1;
}

extern "C" __global__ void __launch_bounds__(NTHR, 1) rnn_persistent(
    const float* __restrict__ h_0,
    const float* __restrict__ W_hh0,
    const float* __restrict__ W_ih1,
    const float* __restrict__ W_hh1,
    const float* __restrict__ b_ih1,
    const float* __restrict__ b_hh1,
    float* __restrict__ out)
{
    extern __shared__ float smem[];
    float* WaS = smem;             // [256][32]  32 KB  (phase A slice)
    float* WbS = smem + 8192;      // [512][32]  64 KB  (phase B slice)
    float* Hs  = smem + 24576;     // [2][32][64] 16 KB

    const int c   = blockIdx.x;
    const int tid = threadIdx.x;

    // roles
    const int jt   = c >> 2;             // 0..31 (shared by both phases)
    const int j0   = jt * 32;
    const int kqA  = c & 3;              // phase A: K quarter
    const int k0A  = kqA * 256;
    const int sb   = c & 3;              // phase B sub: bit1 = matrix, bit0 = K half
    const int matB = sb >> 1;
    const int khB  = sb & 1;
    const int k0B  = khB * 512;
    const float* WBsrc = matB ? W_hh1 : W_ih1;

    // ---- load resident weight slices, transposed to [k][j] ----
    {
        int j  = tid >> 3;               // 0..31
        int ks = (tid & 7) * 32;         // phase A: 32 k each
        const float* wa = W_hh0 + (size_t)(j0 + j) * HDIM + k0A + ks;
        #pragma unroll 8
        for (int k = 0; k < 32; k++) WaS[(ks + k) * 32 + j] = wa[k];
        int ksb = (tid & 7) * 64;        // phase B: 64 k each
        const float* wb = WBsrc + (size_t)(j0 + j) * HDIM + k0B + ksb;
        #pragma unroll 8
        for (int k = 0; k < 64; k++) WbS[(ksb + k) * 32 + j] = wb[k];
    }

    // ---- initial state transpose: h_0[layer][b][k] -> g_h{0,1}T[k][b] ----
    #pragma unroll
    for (int r = 0; r < 2; r++) {
        int e = c * 512 + tid + r * 256;
        int j = e >> 6, b = e & 63;
        g_h0T[e] = h_0[(size_t)b * HDIM + j];
        g_h1T[e] = h_0[(size_t)BH + (size_t)b * HDIM + j];
    }

    unsigned gen = 0;
    if (tid == 0) gen = *(volatile unsigned*)&g_gen;
    grid_barrier(gen);   // weights (per-CTA, via its __syncthreads) + states ready

    for (int t = 0; t < T_STEPS; t++) {
        // ---- phase A: ppA[kq] = W_hh0[j0:,k0A:] @ h0T ----
        gemm_phase(WaS, g_h0T + (size_t)k0A * 64, g_ppA[kqA] + (size_t)j0 * 64,
                   Hs, 256, tid);
        grid_barrier(gen);

        // ---- combine A: h0T = tanh(X0T[t] + sum ppA) ----
        #pragma unroll
        for (int r = 0; r < 2; r++) {
            int e = c * 512 + tid + r * 256;
            float v = g_X0T[(size_t)t * BH + e]
                    + g_ppA[0][e] + g_ppA[1][e] + g_ppA[2][e] + g_ppA[3][e];
            g_h0T[e] = tanhf(v);
        }
        grid_barrier(gen);

        // ---- phase B: ppB[sb] = W[mat][j0:,k0B:] @ h{0|1}T ----
        {
            const float* hsrc = (matB ? g_h1T : g_h0T) + (size_t)k0B * 64;
            gemm_phase(WbS, hsrc, g_ppB[sb] + (size_t)j0 * 64, Hs, 512, tid);
        }
        grid_barrier(gen);

        // ---- combine B: out[t] = tanh(bias1 + sum ppB); update h1T ----
        #pragma unroll
        for (int r = 0; r < 2; r++) {
            int e = c * 512 + tid + r * 256;
            int j = e >> 6, b = e & 63;
            float v = b_ih1[j] + b_hh1[j]
                    + g_ppB[0][e] + g_ppB[1][e] + g_ppB[2][e] + g_ppB[3][e];
            float rr = tanhf(v);
            g_h1T[e] = rr;
            out[(size_t)t * BH + (size_t)b * HDIM + j] = rr;
        }
        grid_barrier(gen);
    }

    // ---- tail: h_n = [h0_final, h1_final] in [b][h] layout ----
    #pragma unroll
    for (int r = 0; r < 2; r++) {
        int e = c * 512 + tid + r * 256;
        int j = e >> 6, b = e & 63;
        out[(size_t)T_STEPS * BH + (size_t)b * HDIM + j]      = g_h0T[e];
        out[(size_t)T_STEPS * BH + BH + (size_t)b * HDIM + j] = g_h1T[e];
    }
}

// =================================================================
// Launch
// =================================================================
extern "C" void kernel_launch(void* const* d_in, const int* in_sizes, int n_in,
                              void* d_out, int out_size)
{
    const float* input = (const float*)d_in[0];
    const float* h_0   = (const float*)d_in[1];
    const float* W_ih0 = (const float*)d_in[2];
    const float* b_ih0 = (const float*)d_in[3];
    const float* W_hh0 = (const float*)d_in[4];
    const float* b_hh0 = (const float*)d_in[5];
    const float* W_ih1 = (const float*)d_in[6];
    const float* b_ih1 = (const float*)d_in[7];
    const float* W_hh1 = (const float*)d_in[8];
    const float* b_hh1 = (const float*)d_in[9];
    float* out = (float*)d_out;

    (void)in_sizes; (void)n_in; (void)out_size;

    const int SMEM_BYTES = (8192 + 16384 + 4096) * 4;   // 114688
    static int configured = 0;
    if (!configured) {
        cudaFuncSetAttribute(rnn_persistent,
                             cudaFuncAttributeMaxDynamicSharedMemorySize,
                             SMEM_BYTES);
        configured = 1;
    }

    // 1) X0T = input @ W_ih0^T + b_ih0 + b_hh0   (transposed store, no seq dep)
    {
        dim3 grid(HDIM / 64, T_STEPS);   // one blockIdx.y per time step (64 rows)
        precompute_kernel<<<grid, 256>>>(input, W_ih0, b_ih0, b_hh0);
    }

    // 2) persistent recurrence (single kernel, 2048 software grid barriers)
    rnn_persistent<<<NCTA, NTHR, SMEM_BYTES>>>(h_0, W_hh0, W_ih1, W_hh1,
                                               b_ih1, b_hh1, out);
}

// round 12
// speedup vs baseline: 1.3184x; 1.3184x over previous
#include <cuda_runtime.h>
#include <math.h>

#define T_STEPS 512
#define BATCH   64
#define INDIM   1024
#define HDIM    1024
#define BH      (BATCH * HDIM)      // 65536
#define NCTA    128
#define NTHR    256

typedef unsigned long long ull;

// ---------------- packed f32x2 helpers ----------------
__device__ __forceinline__ ull fma2(ull a, ull b, ull c) {
    ull d; asm("fma.rn.f32x2 %0, %1, %2, %3;" : "=l"(d) : "l"(a), "l"(b), "l"(c));
    return d;
}
__device__ __forceinline__ ull add2(ull a, ull b) {
    ull d; asm("add.rn.f32x2 %0, %1, %2;" : "=l"(d) : "l"(a), "l"(b));
    return d;
}
__device__ __forceinline__ ull pack2(float x, float y) {
    ull d; asm("mov.b64 %0, {%1, %2};" : "=l"(d) : "f"(x), "f"(y));
    return d;
}
__device__ __forceinline__ float2 unpack2(ull v) {
    float2 r; asm("mov.b64 {%0, %1}, %2;" : "=f"(r.x), "=f"(r.y) : "l"(v));
    return r;
}

// ---------------- device scratch (static, allowed) ----------------
__device__ float g_X0T[(size_t)T_STEPS * BH]; // input proj + layer-0 biases, [t][j][b]
__device__ float g_h0T[BH];                   // layer-0 hidden, [k][b]
__device__ float g_h1T[BH];                   // layer-1 hidden, [k][b]
__device__ float g_ppA[4][BH];                // phase-A CTA-ksplit partials, [sub][j*64+b]
__device__ float g_ppB[4][BH];                // phase-B partials
__device__ unsigned g_cnt;                    // barrier arrival counter
__device__ unsigned g_gen;                    // barrier generation

// =================================================================
// Precompute: X0T[t][n][b] = sum_k input[t*64+b, k]*W_ih0[n,k] + b_ih0[n]+b_hh0[n]
// 128x128x16 tile, 8x8 thread tile, f32x2 packed along n.
// =================================================================
__global__ __launch_bounds__(256) void precompute_kernel(
    const float* __restrict__ X,    // [T*B, IN]
    const float* __restrict__ W,    // [H, IN]
    const float* __restrict__ b1,
    const float* __restrict__ b2)
{
    __shared__ float As[16][128];
    __shared__ float Bs[16][128];

    const int tid = threadIdx.x;
    const int n0 = blockIdx.x * 128;
    const int m0 = blockIdx.y * 128;

    const int lr = tid >> 1;            // 0..127
    const int lk = (tid & 1) * 8;       // 0,8
    const int tm = (tid >> 4) * 8;      // row group
    const int tn = (tid & 15) * 8;      // col group

    ull acc[8][4];
    #pragma unroll
    for (int m = 0; m < 8; m++)
        #pragma unroll
        for (int np = 0; np < 4; np++) acc[m][np] = 0ull;

    for (int k0 = 0; k0 < INDIM; k0 += 16) {
        float4 xa = *(const float4*)&X[(size_t)(m0 + lr) * INDIM + k0 + lk];
        float4 xb = *(const float4*)&X[(size_t)(m0 + lr) * INDIM + k0 + lk + 4];
        float4 wa = *(const float4*)&W[(size_t)(n0 + lr) * INDIM + k0 + lk];
        float4 wb = *(const float4*)&W[(size_t)(n0 + lr) * INDIM + k0 + lk + 4];
        __syncthreads();
        As[lk + 0][lr] = xa.x; As[lk + 1][lr] = xa.y; As[lk + 2][lr] = xa.z; As[lk + 3][lr] = xa.w;
        As[lk + 4][lr] = xb.x; As[lk + 5][lr] = xb.y; As[lk + 6][lr] = xb.z; As[lk + 7][lr] = xb.w;
        Bs[lk + 0][lr] = wa.x; Bs[lk + 1][lr] = wa.y; Bs[lk + 2][lr] = wa.z; Bs[lk + 3][lr] = wa.w;
        Bs[lk + 4][lr] = wb.x; Bs[lk + 5][lr] = wb.y; Bs[lk + 6][lr] = wb.z; Bs[lk + 7][lr] = wb.w;
        __syncthreads();
        #pragma unroll
        for (int kk = 0; kk < 16; kk++) {
            float4 a0 = *(const float4*)&As[kk][tm];
            float4 a1 = *(const float4*)&As[kk][tm + 4];
            ulonglong2 w01 = *(const ulonglong2*)&Bs[kk][tn];
            ulonglong2 w23 = *(const ulonglong2*)&Bs[kk][tn + 4];
            ull wp[4] = {w01.x, w01.y, w23.x, w23.y};
            float am[8] = {a0.x, a0.y, a0.z, a0.w, a1.x, a1.y, a1.z, a1.w};
            #pragma unroll
            for (int m = 0; m < 8; m++) {
                ull ad = pack2(am[m], am[m]);
                #pragma unroll
                for (int np = 0; np < 4; np++)
                    acc[m][np] = fma2(ad, wp[np], acc[m][np]);
            }
        }
    }

    float bs[8];
    #pragma unroll
    for (int j = 0; j < 8; j++) bs[j] = b1[n0 + tn + j] + b2[n0 + tn + j];

    #pragma unroll
    for (int m = 0; m < 8; m++) {
        int row = m0 + tm + m;
        int t = row >> 6, b = row & 63;
        #pragma unroll
        for (int np = 0; np < 4; np++) {
            float2 v = unpack2(acc[m][np]);
            int col = n0 + tn + 2 * np;
            g_X0T[(size_t)t * BH + (size_t)col * 64 + b]       = v.x + bs[2 * np];
            g_X0T[(size_t)t * BH + (size_t)(col + 1) * 64 + b] = v.y + bs[2 * np + 1];
        }
    }
}

// =================================================================
// Persistent recurrent kernel
// =================================================================
__device__ __forceinline__ void grid_barrier(unsigned& gen)
{
    __syncthreads();
    if (threadIdx.x == 0) {
        __threadfence();
        unsigned a = atomicAdd(&g_cnt, 1u);
        if (a == NCTA - 1) {
            g_cnt = 0;
            __threadfence();
            atomicAdd(&g_gen, 1u);
        } else {
            while (*(volatile unsigned*)&g_gen == gen) { }
            __threadfence();
        }
    }
    __syncthreads();
    gen++;
}

// Stage one 256k x 64b h panel (64 KB) from global into smem.
__device__ __forceinline__ void stage_panel(float* Hs, const float* __restrict__ src, int tid)
{
    const float4* s = (const float4*)src;
    float4* d = (float4*)Hs;
    #pragma unroll
    for (int i = 0; i < 16; i++) d[i * 256 + tid] = s[i * 256 + tid];
}

// One 256-k panel of the GEMM.  Wp: [256][32] k-major; Hs: [256][64].
// Thread (ksub,bgrp,jgrp) accumulates 4j x 16b (8 b-pairs) over its 32 k.
__device__ __forceinline__ void gemm32(
    const float* __restrict__ Wp, const float* __restrict__ Hs,
    int ksub, int jgrp, int bgrp, ull acc[4][8])
{
    const float* wrow = Wp + (ksub * 32) * 32 + jgrp * 4;
    const float* hrow = Hs + (ksub * 32) * 64 + bgrp * 16;
    #pragma unroll 4
    for (int kk = 0; kk < 32; kk++) {
        float4 w = *(const float4*)(wrow + kk * 32);
        ulonglong2 hA = *(const ulonglong2*)(hrow + kk * 64);
        ulonglong2 hB = *(const ulonglong2*)(hrow + kk * 64 + 4);
        ulonglong2 hC = *(const ulonglong2*)(hrow + kk * 64 + 8);
        ulonglong2 hD = *(const ulonglong2*)(hrow + kk * 64 + 12);
        ull wd0 = pack2(w.x, w.x), wd1 = pack2(w.y, w.y);
        ull wd2 = pack2(w.z, w.z), wd3 = pack2(w.w, w.w);
        ull hh[8] = {hA.x, hA.y, hB.x, hB.y, hC.x, hC.y, hD.x, hD.y};
        #pragma unroll
        for (int p = 0; p < 8; p++) {
            acc[0][p] = fma2(wd0, hh[p], acc[0][p]);
            acc[1][p] = fma2(wd1, hh[p], acc[1][p]);
            acc[2][p] = fma2(wd2, hh[p], acc[2][p]);
            acc[3][p] = fma2(wd3, hh[p], acc[3][p]);
        }
    }
}

// Reduce the 8 ksub partials through smem (Red aliases Hs) and store the
// CTA's partial tile to gdst (= g_pp[sub] + j0*64).  Deterministic order.
__device__ __forceinline__ void reduce_store(
    float* Red, ull acc[4][8], float* __restrict__ gdst, int tid)
{
    __syncthreads();                       // all Hs reads complete (Red aliases Hs)
    ull* rw = (ull*)Red;                   // layout: [col(32)][tid(256)] in ull units
    #pragma unroll
    for (int j = 0; j < 4; j++)
        #pragma unroll
        for (int p = 0; p < 8; p++)
            rw[(j * 8 + p) * 256 + tid] = acc[j][p];
    __syncthreads();

    const int rowidx = tid & 31;           // = bgrp*8 + jgrp of source threads
    const int grp    = tid >> 5;
    const int jgrp_o = rowidx & 7;
    const int bgrp_o = rowidx >> 3;
    #pragma unroll
    for (int q = 0; q < 4; q++) {
        int col = grp * 4 + q;             // = j*8 + p
        ull s = rw[col * 256 + rowidx];
        #pragma unroll
        for (int ks = 1; ks < 8; ks++)
            s = add2(s, rw[col * 256 + ks * 32 + rowidx]);
        int jj = col >> 3, p = col & 7;
        int jl = jgrp_o * 4 + jj;
        int b  = bgrp_o * 16 + 2 * p;
        float2 v = unpack2(s);
        *(float2*)&gdst[jl * 64 + b] = v;
    }
}

extern "C" __global__ void __launch_bounds__(NTHR, 1) rnn_persistent(
    const float* __restrict__ h_0,
    const float* __restrict__ W_hh0,
    const float* __restrict__ W_ih1,
    const float* __restrict__ W_hh1,
    const float* __restrict__ b_ih1,
    const float* __restrict__ b_hh1,
    float* __restrict__ out)
{
    extern __shared__ float smem[];
    float* WaS = smem;             // [256][32]  32 KB  (phase-A weight slice)
    float* WbS = smem + 8192;      // [512][32]  64 KB  (phase-B weight slice)
    float* Hs  = smem + 24576;     // [256][64]  64 KB  h panel; aliased as Red

    const int c   = blockIdx.x;
    const int tid = threadIdx.x;

    const int jt  = c >> 2, j0 = jt * 32;
    const int sub = c & 3;
    const int k0A = sub * 256;                 // phase A: K quarter
    const int matB = sub >> 1, khB = sub & 1;  // phase B: matrix / K half
    const int k0B = khB * 512;
    const float* WBsrc = matB ? W_hh1 : W_ih1;

    const int ksub = tid >> 5;
    const int bgrp = (tid >> 3) & 3;
    const int jgrp = tid & 7;

    // ---- resident weight slices, transposed to [k][j] ----
    {
        int j  = tid >> 3;
        int kc = tid & 7;
        const float* wa = W_hh0 + (size_t)(j0 + j) * HDIM + k0A + kc * 32;
        #pragma unroll 8
        for (int k = 0; k < 32; k++) WaS[(kc * 32 + k) * 32 + j] = wa[k];
        const float* wb = WBsrc + (size_t)(j0 + j) * HDIM + k0B + kc * 64;
        #pragma unroll 8
        for (int k = 0; k < 64; k++) WbS[(kc * 64 + k) * 32 + j] = wb[k];
    }

    // ---- initial state transpose: h_0[layer][b][k] -> g_h{0,1}T[k][b] ----
    #pragma unroll
    for (int r = 0; r < 2; r++) {
        int e = c * 512 + tid + r * 256;
        int j = e >> 6, b = e & 63;
        g_h0T[e] = h_0[(size_t)b * HDIM + j];
        g_h1T[e] = h_0[(size_t)BH + (size_t)b * HDIM + j];
    }

    unsigned gen = 0;
    if (tid == 0) gen = *(volatile unsigned*)&g_gen;
    grid_barrier(gen);

    for (int t = 0; t < T_STEPS; t++) {
        // ===== SLOT 1: combineB(t-1) + gemmA(t) =====
        if (t > 0) {
            #pragma unroll
            for (int r = 0; r < 2; r++) {
                int e = c * 512 + tid + r * 256;
                int j = e >> 6, b = e & 63;
                float v = b_ih1[j] + b_hh1[j]
                        + g_ppB[0][e] + g_ppB[1][e] + g_ppB[2][e] + g_ppB[3][e];
                float rr = tanhf(v);
                g_h1T[e] = rr;
                out[(size_t)(t - 1) * BH + (size_t)b * HDIM + j] = rr;
            }
        }
        {
            ull acc[4][8];
            #pragma unroll
            for (int j = 0; j < 4; j++)
                #pragma unroll
                for (int p = 0; p < 8; p++) acc[j][p] = 0ull;
            stage_panel(Hs, g_h0T + (size_t)k0A * 64, tid);
            __syncthreads();
            gemm32(WaS, Hs, ksub, jgrp, bgrp, acc);
            reduce_store(Hs, acc, g_ppA[sub] + (size_t)j0 * 64, tid);
        }
        grid_barrier(gen);

        // ===== SLOT 2: combineA(t): h0T = tanh(X0T[t] + sum ppA) =====
        #pragma unroll
        for (int r = 0; r < 2; r++) {
            int e = c * 512 + tid + r * 256;
            float v = g_X0T[(size_t)t * BH + e]
                    + g_ppA[0][e] + g_ppA[1][e] + g_ppA[2][e] + g_ppA[3][e];
            g_h0T[e] = tanhf(v);
        }
        grid_barrier(gen);

        // ===== SLOT 3: gemmB(t): ppB[sub] over [W_ih1 | W_hh1] k-range =====
        {
            const float* hb = (matB ? g_h1T : g_h0T) + (size_t)k0B * 64;
            ull acc[4][8];
            #pragma unroll
            for (int j = 0; j < 4; j++)
                #pragma unroll
                for (int p = 0; p < 8; p++) acc[j][p] = 0ull;
            stage_panel(Hs, hb, tid);
            __syncthreads();
            gemm32(WbS, Hs, ksub, jgrp, bgrp, acc);
            __syncthreads();
            stage_panel(Hs, hb + 256 * 64, tid);
            __syncthreads();
            gemm32(WbS + 256 * 32, Hs, ksub, jgrp, bgrp, acc);
            reduce_store(Hs, acc, g_ppB[sub] + (size_t)j0 * 64, tid);
        }
        grid_barrier(gen);
    }

    // ===== final combineB(T-1) + h_n tail =====
    #pragma unroll
    for (int r = 0; r < 2; r++) {
        int e = c * 512 + tid + r * 256;
        int j = e >> 6, b = e & 63;
        float v = b_ih1[j] + b_hh1[j]
                + g_ppB[0][e] + g_ppB[1][e] + g_ppB[2][e] + g_ppB[3][e];
        float rr = tanhf(v);
        out[(size_t)(T_STEPS - 1) * BH + (size_t)b * HDIM + j] = rr;
        out[(size_t)T_STEPS * BH + BH + (size_t)b * HDIM + j]  = rr;       // h1_n
        out[(size_t)T_STEPS * BH + (size_t)b * HDIM + j]       = g_h0T[e]; // h0_n
    }
}

// =================================================================
// Launch
// =================================================================
extern "C" void kernel_launch(void* const* d_in, const int* in_sizes, int n_in,
                              void* d_out, int out_size)
{
    const float* input = (const float*)d_in[0];
    const float* h_0   = (const float*)d_in[1];
    const float* W_ih0 = (const float*)d_in[2];
    const float* b_ih0 = (const float*)d_in[3];
    const float* W_hh0 = (const float*)d_in[4];
    const float* b_hh0 = (const float*)d_in[5];
    const float* W_ih1 = (const float*)d_in[6];
    const float* b_ih1 = (const float*)d_in[7];
    const float* W_hh1 = (const float*)d_in[8];
    const float* b_hh1 = (const float*)d_in[9];
    float* out = (float*)d_out;

    (void)in_sizes; (void)n_in; (void)out_size;

    const int SMEM_BYTES = (8192 + 16384 + 16384) * 4;   // 163840
    cudaFuncSetAttribute(rnn_persistent,
                         cudaFuncAttributeMaxDynamicSharedMemorySize,
                         SMEM_BYTES);

    // 1) X0T = input @ W_ih0^T + b_ih0 + b_hh0
    {
        dim3 grid(HDIM / 128, (T_STEPS * BATCH) / 128);
        precompute_kernel<<<grid, 256>>>(input, W_ih0, b_ih0, b_hh0);
    }

    // 2) persistent recurrence (single kernel, 3 barriers/step)
    rnn_persistent<<<NCTA, NTHR, SMEM_BYTES>>>(h_0, W_hh0, W_ih1, W_hh1,
                                               b_ih1, b_hh1, out);
}